// round 16
// baseline (speedup 1.0000x reference)
#include <cuda_runtime.h>

#define NN 10000
#define TT 50
#define Bn 2
#define Hn 64
#define BH 128          // Bn*Hn
#define IND 128         // input feature dim
#define EMAX 160000
#define GRID 592        // 148 SMs x 4 blocks -- co-resident via __launch_bounds__(256,4)
#define NPB 17          // nodes per block: 592*17 = 10064 >= 10000
#define WSTRIDE 34      // u64 pairs per j row in Wp_s (32 + 2 pad, 16B-aligned rows)

typedef unsigned long long u64;
typedef unsigned int u32;

// ---------------- device scratch (no allocation allowed) ----------------
__device__ float d_h[2][NN * BH];           // double-buffered fp32 hidden state [node][b*H+h]
__device__ int   d_deg_in[NN];
__device__ int   d_deg_out[NN];
__device__ float d_norm_s[NN];
__device__ float d_norm_d[NN];
__device__ int   d_row_ptr[NN + 1];
__device__ int   d_fill_ptr[NN];
__device__ __align__(16) u64 d_csr[2 * EMAX];  // per edge: [src | (w,w) f32x2]  (ulonglong2)
__device__ int   g_bar;                     // global barrier arrivals (static zero-init)
__device__ int   g_gen;                     // global barrier generation

// ---------------- packed f32x2 helpers (Blackwell FFMA2) ----------------
__device__ __forceinline__ u64 pk32(u32 lo, u32 hi) {
    u64 r; asm("mov.b64 %0, {%1, %2};" : "=l"(r) : "r"(lo), "r"(hi)); return r;
}
__device__ __forceinline__ void unpack2(u64 v, float& lo, float& hi) {
    asm("mov.b64 {%0, %1}, %2;" : "=f"(lo), "=f"(hi) : "l"(v));
}
__device__ __forceinline__ void ffma2(u64& d, u64 a, u64 b) {
    asm("fma.rn.f32x2 %0, %1, %2, %0;" : "+l"(d) : "l"(a), "l"(b));
}

// sense-reversing grid-wide barrier (all GRID blocks co-resident)
__device__ __forceinline__ void grid_barrier() {
    __syncthreads();
    if (threadIdx.x == 0) {
        __threadfence();
        int gen = *(volatile int*)&g_gen;
        if (atomicAdd(&g_bar, 1) == GRID - 1) {
            g_bar = 0;
            __threadfence();
            atomicAdd(&g_gen, 1);
        } else {
            while (*(volatile int*)&g_gen == gen) { }
            __threadfence();
        }
    }
    __syncthreads();
}

__device__ __forceinline__ float fsigm(float x) {
    return __fdividef(1.f, 1.f + __expf(-x));
}

// ================= ONE kernel: precompute + all 50 GCN-GRU timesteps =================
__global__ __launch_bounds__(256, 4) void mega_kernel(
    const float* __restrict__ x,
    const int*   __restrict__ src,  const int* __restrict__ dst,
    const float* __restrict__ wr,   const float* __restrict__ br,
    const float* __restrict__ wz,   const float* __restrict__ bz,
    const float* __restrict__ wh,   const float* __restrict__ bh,
    const float* __restrict__ gcn_w, const float* __restrict__ gcn_b,
    float* __restrict__ out, int E) {

    __shared__ __align__(16) float agg_s[2 * NPB * 64];   // item-major: row(it) = it*64
    __shared__ __align__(16) u64   Wp_s[64 * WSTRIDE];    // W columns as f32x2 pairs [j][kp]
    __shared__ float xg_s[3 * BH];                        // xr|xz|xh projections
    __shared__ int   wsum_s[8];

    int tid  = threadIdx.x;
    int warp = tid >> 5, lane = tid & 31;
    int gtid = blockIdx.x * 256 + tid;
    int gstride = GRID * 256;

    int node0 = blockIdx.x * NPB;
    int nb = NN - node0;
    if (nb > NPB) nb = NPB;
    if (nb < 0) nb = 0;
    int nb2 = nb * 2;

    // ---------- pre 0: zero state + degree arrays; per-block xproj + W pack ----------
    for (int i = gtid; i < NN * BH / 4; i += gstride)
        ((float4*)d_h[0])[i] = make_float4(0.f, 0.f, 0.f, 0.f);
    for (int i = gtid; i < NN; i += gstride) { d_deg_in[i] = 0; d_deg_out[i] = 0; }
    // xproj into xg_s (agg_s as x staging)
    if (tid < Bn * IND) agg_s[tid] = x[tid];
    __syncthreads();
    for (int i = tid; i < 3 * BH; i += 256) {
        int p = i / BH, r = i % BH, b = r / Hn, j = r % Hn;
        const float* W    = (p == 0) ? wr : (p == 1) ? wz : wh;
        const float* bias = (p == 0) ? br : (p == 1) ? bz : bh;
        float s = bias[j];
        #pragma unroll 8
        for (int k = 0; k < IND; k++)
            s += agg_s[b * IND + k] * W[k * Hn + j];
        xg_s[i] = s;
    }
    // pack W into smem: Wp_s[j*WSTRIDE + kp] = f32x2(W[2kp][j], W[2kp+1][j])
    for (int i = tid; i < 64 * 32; i += 256) {
        int j = i >> 5, kp = i & 31;
        Wp_s[j * WSTRIDE + kp] = pk32(__float_as_uint(gcn_w[(2 * kp) * 64 + j]),
                                      __float_as_uint(gcn_w[(2 * kp + 1) * 64 + j]));
    }
    __syncthreads();
    grid_barrier();   // degrees zeroed everywhere

    // ---------- pre 1: degree histogram ----------
    for (int e = gtid; e < E; e += gstride) {
        atomicAdd(&d_deg_out[src[e]], 1);
        atomicAdd(&d_deg_in[dst[e]], 1);
    }
    grid_barrier();

    // ---------- pre 2: norms (all blocks) + exclusive scan (block 0) ----------
    for (int i = gtid; i < NN; i += gstride) {
        d_norm_s[i] = rsqrtf((float)max(d_deg_out[i], 1));
        d_norm_d[i] = rsqrtf((float)max(d_deg_in[i], 1));
    }
    if (blockIdx.x == 0) {
        const int PER = (NN + 255) / 256;       // 40 contiguous elems per thread
        int base = tid * PER;
        int s = 0;
        for (int k = 0; k < PER; k++) {
            int i = base + k;
            if (i < NN) s += d_deg_in[i];
        }
        int ps = s;
        #pragma unroll
        for (int off = 1; off < 32; off <<= 1) {
            int tv = __shfl_up_sync(0xffffffffu, ps, off);
            if (lane >= off) ps += tv;
        }
        if (lane == 31) wsum_s[warp] = ps;
        __syncthreads();
        if (warp == 0 && lane < 8) {
            int v = wsum_s[lane];
            #pragma unroll
            for (int off = 1; off < 8; off <<= 1) {
                int tv = __shfl_up_sync(0xffu, v, off);
                if (lane >= off) v += tv;
            }
            wsum_s[lane] = v;
        }
        __syncthreads();
        int warpoff = (warp == 0) ? 0 : wsum_s[warp - 1];
        int run = warpoff + ps - s;             // exclusive prefix
        for (int k = 0; k < PER; k++) {
            int i = base + k;
            if (i < NN) {
                d_row_ptr[i] = run;
                d_fill_ptr[i] = run;
                run += d_deg_in[i];
            }
        }
        if (tid == 255) d_row_ptr[NN] = wsum_s[7];
        __syncthreads();
    }
    grid_barrier();

    // ---------- pre 3: CSR scatter with fused, pre-duplicated edge weight ----------
    for (int e = gtid; e < E; e += gstride) {
        int s = src[e], d = dst[e];
        int pos = atomicAdd(&d_fill_ptr[d], 1);
        u32 wb = __float_as_uint(d_norm_d[d] * d_norm_s[s]);
        ((ulonglong2*)d_csr)[pos] = make_ulonglong2((u64)(u32)s, pk32(wb, wb));
    }

    // ---------- per-thread persistent constants ----------
    int j  = tid & 63;                  // output channel
    int pg = tid >> 6;                  // item group 0..3
    float xr0 = xg_s[j],        xr1 = xg_s[64 + j];
    float xz0 = xg_s[128 + j],  xz1 = xg_s[192 + j];
    float xh0 = xg_s[256 + j],  xh1 = xg_s[320 + j];
    float bias_j = gcn_b[j];

    grid_barrier();   // csr + h[0] ready everywhere

    // ================= 50 timesteps =================
    for (int t = 0; t < TT; t++) {
        const float* __restrict__ h_prev = d_h[t & 1];
        float*       __restrict__ h_next = d_h[(t & 1) ^ 1];

        // ---- phase 1: CSR gather, 1 node/warp, MLP-2, pure FFMA2 ----
        int lane4 = lane * 4;
        for (int ln = warp; ln < nb; ln += 8) {
            int node = node0 + ln;
            int p = __ldg(&d_row_ptr[node]), e = __ldg(&d_row_ptr[node + 1]);
            u64 a01 = 0, a23 = 0;
            for (; p + 2 <= e; p += 2) {
                ulonglong2 c0 = __ldg((const ulonglong2*)d_csr + p);
                ulonglong2 c1 = __ldg((const ulonglong2*)d_csr + p + 1);
                uint4 v0 = __ldcg((const uint4*)&h_prev[(int)c0.x * BH + lane4]);
                uint4 v1 = __ldcg((const uint4*)&h_prev[(int)c1.x * BH + lane4]);
                ffma2(a01, c0.y, pk32(v0.x, v0.y));
                ffma2(a23, c0.y, pk32(v0.z, v0.w));
                ffma2(a01, c1.y, pk32(v1.x, v1.y));
                ffma2(a23, c1.y, pk32(v1.z, v1.w));
            }
            if (p < e) {
                ulonglong2 c0 = __ldg((const ulonglong2*)d_csr + p);
                uint4 v0 = __ldcg((const uint4*)&h_prev[(int)c0.x * BH + lane4]);
                ffma2(a01, c0.y, pk32(v0.x, v0.y));
                ffma2(a23, c0.y, pk32(v0.z, v0.w));
            }
            // agg row(it)=it*64; node row covers it=2ln (ch 0..63) and 2ln+1 (64..127)
            ulonglong2 st; st.x = a01; st.y = a23;
            *(ulonglong2*)&agg_s[ln * BH + lane4] = st;
        }
        __syncthreads();

        // ---- phase 2: g = agg @ W + b, 4 items per group, FFMA2 from packed smem ----
        for (int base = 0; base < nb2; base += 16) {
            int it0 = base + pg * 4;
            int i0 = it0,     v0 = (i0 < nb2); if (!v0) i0 = 0;
            int i1 = it0 + 1, v1 = (i1 < nb2); if (!v1) i1 = 0;
            int i2 = it0 + 2, v2 = (i2 < nb2); if (!v2) i2 = 0;
            int i3 = it0 + 3, v3 = (i3 < nb2); if (!v3) i3 = 0;

            // prefetch h_prev for the update (own nodes; only this block writes them)
            int n0 = node0 + (i0 >> 1), bj0 = ((i0 & 1) << 6) + j;
            int n1 = node0 + (i1 >> 1), bj1 = ((i1 & 1) << 6) + j;
            int n2 = node0 + (i2 >> 1), bj2 = ((i2 & 1) << 6) + j;
            int n3 = node0 + (i3 >> 1), bj3 = ((i3 & 1) << 6) + j;
            float hold0 = h_prev[n0 * BH + bj0];
            float hold1 = h_prev[n1 * BH + bj1];
            float hold2 = h_prev[n2 * BH + bj2];
            float hold3 = h_prev[n3 * BH + bj3];

            u64 G0 = 0, G1 = 0, G2 = 0, G3 = 0;
            const u64* wrow = &Wp_s[j * WSTRIDE];
            #pragma unroll
            for (int k2 = 0; k2 < 16; k2++) {
                ulonglong2 wp = *(const ulonglong2*)&wrow[2 * k2];
                ulonglong2 a0 = *(const ulonglong2*)&agg_s[i0 * 64 + k2 * 4];
                ulonglong2 a1 = *(const ulonglong2*)&agg_s[i1 * 64 + k2 * 4];
                ulonglong2 a2 = *(const ulonglong2*)&agg_s[i2 * 64 + k2 * 4];
                ulonglong2 a3 = *(const ulonglong2*)&agg_s[i3 * 64 + k2 * 4];
                ffma2(G0, a0.x, wp.x); ffma2(G0, a0.y, wp.y);
                ffma2(G1, a1.x, wp.x); ffma2(G1, a1.y, wp.y);
                ffma2(G2, a2.x, wp.x); ffma2(G2, a2.y, wp.y);
                ffma2(G3, a3.x, wp.x); ffma2(G3, a3.y, wp.y);
            }

            #define EPILOG(G, ii, vv, nn, bb, hold)                                   \
                if (vv) {                                                             \
                    float glo, ghi; unpack2(G, glo, ghi);                             \
                    float g = glo + ghi + bias_j;                                     \
                    int bsel = ii & 1;                                                \
                    float xr = bsel ? xr1 : xr0;                                      \
                    float xz = bsel ? xz1 : xz0;                                      \
                    float xh = bsel ? xh1 : xh0;                                      \
                    float r = fsigm(xr + g);                                          \
                    float z = fsigm(xz + g);                                          \
                    float ht = 2.f * fsigm(2.f * (xh + r * g)) - 1.f;                 \
                    float hn = hold + z * (ht - hold);                                \
                    h_next[nn * BH + bb] = hn;                                        \
                    out[((size_t)(bsel * TT + t) * NN + nn) * Hn + j] = hn;           \
                }
            EPILOG(G0, i0, v0, n0, bj0, hold0)
            EPILOG(G1, i1, v1, n1, bj1, hold1)
            EPILOG(G2, i2, v2, n2, bj2, hold2)
            EPILOG(G3, i3, v3, n3, bj3, hold3)
            #undef EPILOG
        }

        grid_barrier();   // h_next published before next step's gather
    }
}

// ---------------- launch: ONE kernel ----------------
extern "C" void kernel_launch(void* const* d_in, const int* in_sizes, int n_in,
                              void* d_out, int out_size) {
    const float* x    = (const float*)d_in[0];
    const int*   src  = (const int*)  d_in[1];
    const int*   dst  = (const int*)  d_in[2];
    const float* wr   = (const float*)d_in[3];
    const float* br   = (const float*)d_in[4];
    const float* wz   = (const float*)d_in[5];
    const float* bz   = (const float*)d_in[6];
    const float* wh   = (const float*)d_in[7];
    const float* bh   = (const float*)d_in[8];
    const float* gw   = (const float*)d_in[9];
    const float* gb   = (const float*)d_in[10];
    float* out = (float*)d_out;
    int E = in_sizes[1];

    mega_kernel<<<GRID, 256>>>(x, src, dst, wr, br, wz, bz, wh, bh, gw, gb, out, E);
}

// round 17
// speedup vs baseline: 2.5761x; 2.5761x over previous
#include <cuda_runtime.h>
#include <cuda_fp16.h>

#define NN 10000
#define TT 50
#define Bn 2
#define Hn 64
#define BH 128          // Bn*Hn
#define IND 128         // input feature dim
#define EMAX 160000
#define GRID 500        // <= 592 co-resident at occ 4; 500*20 = 10000 exactly
#define NPB 20          // nodes per block

typedef unsigned long long u64;
typedef unsigned int u32;

// ---------------- device scratch (no allocation allowed) ----------------
__device__ __half d_hh[2][NN * BH];         // double-buffered fp16 hidden state (gather operand)
__device__ int    d_deg_in[NN];
__device__ int    d_deg_out[NN];
__device__ float  d_norm_s[NN];
__device__ float  d_norm_d[NN];
__device__ int    d_row_ptr[NN + 1];
__device__ int    d_fill_ptr[NN];
__device__ int2   d_csr[EMAX];              // (src, weight-as-int-bits), 8 B/edge
__device__ int    g_bar;                    // global barrier arrivals (static zero-init)
__device__ int    g_gen;                    // global barrier generation

// ---------------- packed f32x2 helpers (Blackwell FFMA2) ----------------
__device__ __forceinline__ u64 pack2(float lo, float hi) {
    u64 r; asm("mov.b64 %0, {%1, %2};" : "=l"(r) : "f"(lo), "f"(hi)); return r;
}
__device__ __forceinline__ void unpack2(u64 v, float& lo, float& hi) {
    asm("mov.b64 {%0, %1}, %2;" : "=f"(lo), "=f"(hi) : "l"(v));
}
__device__ __forceinline__ void ffma2(u64& d, u64 a, u64 b) {
    asm("fma.rn.f32x2 %0, %1, %2, %0;" : "+l"(d) : "l"(a), "l"(b));
}

// fast tanh (MUFU.TANH, sm_75+): 1 op instead of EX2+RCP chains
__device__ __forceinline__ float ftanh(float x) {
    float r; asm("tanh.approx.f32 %0, %1;" : "=f"(r) : "f"(x)); return r;
}
__device__ __forceinline__ float fsigm(float x) {      // sigmoid via tanh: 1 MUFU + 2 FMA
    return fmaf(0.5f, ftanh(0.5f * x), 0.5f);
}

// accumulate one fp16 message (uint2 = 4 halves) with packed FFMA2
__device__ __forceinline__ void acc_msg(u64& a01, u64& a23, float w, uint2 v) {
    float2 fa = __half22float2(*(__half2*)&v.x);
    float2 fb = __half22float2(*(__half2*)&v.y);
    u64 ww = pack2(w, w);
    ffma2(a01, ww, pack2(fa.x, fa.y));
    ffma2(a23, ww, pack2(fb.x, fb.y));
}

// sense-reversing grid-wide barrier (all GRID blocks co-resident)
__device__ __forceinline__ void grid_barrier() {
    __syncthreads();
    if (threadIdx.x == 0) {
        __threadfence();
        int gen = *(volatile int*)&g_gen;
        if (atomicAdd(&g_bar, 1) == GRID - 1) {
            g_bar = 0;
            __threadfence();
            atomicAdd(&g_gen, 1);
        } else {
            while (*(volatile int*)&g_gen == gen) { }
            __threadfence();
        }
    }
    __syncthreads();
}

// ================= ONE kernel: precompute + all 50 GCN-GRU timesteps =================
__global__ __launch_bounds__(256, 4) void mega_kernel(
    const float* __restrict__ x,
    const int*   __restrict__ src,  const int* __restrict__ dst,
    const float* __restrict__ wr,   const float* __restrict__ br,
    const float* __restrict__ wz,   const float* __restrict__ bz,
    const float* __restrict__ wh,   const float* __restrict__ bh,
    const float* __restrict__ gcn_w, const float* __restrict__ gcn_b,
    float* __restrict__ out, int E) {

    __shared__ __align__(16) float agg_s[NPB * BH];      // item-major: row(it) = it*64
    __shared__ __align__(16) float hs[NPB * BH];         // persistent fp32 h, item-major
    __shared__ __align__(16) u64   Wp_s[32 * 64];        // W f32x2 pairs, kp-major: [kp][j]
    __shared__ float xg_s[3 * BH];                       // xr|xz|xh projections
    __shared__ int   wsum_s[8];

    int tid  = threadIdx.x;
    int warp = tid >> 5, lane = tid & 31;
    int gtid = blockIdx.x * 256 + tid;
    int gstride = GRID * 256;

    int node0 = blockIdx.x * NPB;
    int nb = NN - node0;
    if (nb > NPB) nb = NPB;
    if (nb < 0) nb = 0;
    int nb2 = nb * 2;

    // ---------- pre 0: zero global state + degrees; per-block xproj + W pack ----------
    for (int i = gtid; i < NN * BH / 2; i += gstride)
        ((__half2*)d_hh[0])[i] = __floats2half2_rn(0.f, 0.f);
    for (int i = gtid; i < NN; i += gstride) { d_deg_in[i] = 0; d_deg_out[i] = 0; }
    for (int i = tid; i < NPB * BH; i += 256) hs[i] = 0.f;
    // xproj into xg_s (agg_s as x staging)
    if (tid < Bn * IND) agg_s[tid] = x[tid];
    __syncthreads();
    for (int i = tid; i < 3 * BH; i += 256) {
        int p = i / BH, r = i % BH, b = r / Hn, j = r % Hn;
        const float* W    = (p == 0) ? wr : (p == 1) ? wz : wh;
        const float* bias = (p == 0) ? br : (p == 1) ? bz : bh;
        float s = bias[j];
        #pragma unroll 8
        for (int k = 0; k < IND; k++)
            s += agg_s[b * IND + k] * W[k * Hn + j];
        xg_s[i] = s;
    }
    // pack W kp-major: Wp_s[kp*64 + j] = f32x2(W[2kp][j], W[2kp+1][j]) -- conflict-free LDS64
    for (int i = tid; i < 32 * 64; i += 256) {
        int kp = i >> 6, j = i & 63;
        Wp_s[kp * 64 + j] = pack2(gcn_w[(2 * kp) * 64 + j], gcn_w[(2 * kp + 1) * 64 + j]);
    }
    __syncthreads();
    grid_barrier();   // degrees zeroed everywhere

    // ---------- pre 1: degree histogram ----------
    for (int e = gtid; e < E; e += gstride) {
        atomicAdd(&d_deg_out[src[e]], 1);
        atomicAdd(&d_deg_in[dst[e]], 1);
    }
    grid_barrier();

    // ---------- pre 2: norms (all blocks) + exclusive scan (block 0) ----------
    for (int i = gtid; i < NN; i += gstride) {
        d_norm_s[i] = rsqrtf((float)max(d_deg_out[i], 1));
        d_norm_d[i] = rsqrtf((float)max(d_deg_in[i], 1));
    }
    if (blockIdx.x == 0) {
        const int PER = (NN + 255) / 256;       // 40 contiguous elems per thread
        int base = tid * PER;
        int s = 0;
        for (int k = 0; k < PER; k++) {
            int i = base + k;
            if (i < NN) s += d_deg_in[i];
        }
        int ps = s;
        #pragma unroll
        for (int off = 1; off < 32; off <<= 1) {
            int tv = __shfl_up_sync(0xffffffffu, ps, off);
            if (lane >= off) ps += tv;
        }
        if (lane == 31) wsum_s[warp] = ps;
        __syncthreads();
        if (warp == 0 && lane < 8) {
            int v = wsum_s[lane];
            #pragma unroll
            for (int off = 1; off < 8; off <<= 1) {
                int tv = __shfl_up_sync(0xffu, v, off);
                if (lane >= off) v += tv;
            }
            wsum_s[lane] = v;
        }
        __syncthreads();
        int warpoff = (warp == 0) ? 0 : wsum_s[warp - 1];
        int run = warpoff + ps - s;             // exclusive prefix
        for (int k = 0; k < PER; k++) {
            int i = base + k;
            if (i < NN) {
                d_row_ptr[i] = run;
                d_fill_ptr[i] = run;
                run += d_deg_in[i];
            }
        }
        if (tid == 255) d_row_ptr[NN] = wsum_s[7];
        __syncthreads();
    }
    grid_barrier();

    // ---------- pre 3: CSR scatter with fused edge weight (8 B/edge) ----------
    for (int e = gtid; e < E; e += gstride) {
        int s = src[e], d = dst[e];
        int pos = atomicAdd(&d_fill_ptr[d], 1);
        float w = d_norm_d[d] * d_norm_s[s];
        d_csr[pos] = make_int2(s, __float_as_int(w));
    }

    // ---------- per-thread persistent constants ----------
    int j  = tid & 63;                  // output channel
    int pg = tid >> 6;                  // item group 0..3
    float xr0 = xg_s[j],        xr1 = xg_s[64 + j];
    float xz0 = xg_s[128 + j],  xz1 = xg_s[192 + j];
    float xh0 = xg_s[256 + j],  xh1 = xg_s[320 + j];
    float bias_j = gcn_b[j];

    grid_barrier();   // csr + hh[0] ready everywhere

    // ================= 50 timesteps =================
    for (int t = 0; t < TT; t++) {
        const __half* __restrict__ hh_prev = d_hh[t & 1];
        __half*       __restrict__ hh_next = d_hh[(t & 1) ^ 1];

        // ---- phase 1: dual-stream fp16 CSR gather (round-14 proven) ----
        int lane4 = lane * 4;
        for (int base = 0; base < nb; base += 16) {
            int lnA = base + warp;
            int lnB = base + warp + 8;
            bool actA = lnA < nb, actB = lnB < nb;
            int pA = 0, eA = 0, pB = 0, eB = 0;
            if (actA) { pA = __ldg(&d_row_ptr[node0 + lnA]); eA = __ldg(&d_row_ptr[node0 + lnA + 1]); }
            if (actB) { pB = __ldg(&d_row_ptr[node0 + lnB]); eB = __ldg(&d_row_ptr[node0 + lnB + 1]); }
            u64 a01 = 0, a23 = 0, b01 = 0, b23 = 0;

            while (pA + 2 <= eA && pB + 2 <= eB) {
                int2 ea0 = __ldg(&d_csr[pA]);
                int2 ea1 = __ldg(&d_csr[pA + 1]);
                int2 eb0 = __ldg(&d_csr[pB]);
                int2 eb1 = __ldg(&d_csr[pB + 1]);
                uint2 va0 = __ldcg((const uint2*)&hh_prev[ea0.x * BH + lane4]);
                uint2 va1 = __ldcg((const uint2*)&hh_prev[ea1.x * BH + lane4]);
                uint2 vb0 = __ldcg((const uint2*)&hh_prev[eb0.x * BH + lane4]);
                uint2 vb1 = __ldcg((const uint2*)&hh_prev[eb1.x * BH + lane4]);
                acc_msg(a01, a23, __int_as_float(ea0.y), va0);
                acc_msg(a01, a23, __int_as_float(ea1.y), va1);
                acc_msg(b01, b23, __int_as_float(eb0.y), vb0);
                acc_msg(b01, b23, __int_as_float(eb1.y), vb1);
                pA += 2; pB += 2;
            }
            if (actA) {
                int p = pA;
                for (; p + 4 <= eA; p += 4) {
                    int2 e0 = __ldg(&d_csr[p]);
                    int2 e1 = __ldg(&d_csr[p + 1]);
                    int2 e2 = __ldg(&d_csr[p + 2]);
                    int2 e3 = __ldg(&d_csr[p + 3]);
                    uint2 v0 = __ldcg((const uint2*)&hh_prev[e0.x * BH + lane4]);
                    uint2 v1 = __ldcg((const uint2*)&hh_prev[e1.x * BH + lane4]);
                    uint2 v2 = __ldcg((const uint2*)&hh_prev[e2.x * BH + lane4]);
                    uint2 v3 = __ldcg((const uint2*)&hh_prev[e3.x * BH + lane4]);
                    acc_msg(a01, a23, __int_as_float(e0.y), v0);
                    acc_msg(a01, a23, __int_as_float(e1.y), v1);
                    acc_msg(a01, a23, __int_as_float(e2.y), v2);
                    acc_msg(a01, a23, __int_as_float(e3.y), v3);
                }
                for (; p < eA; p++) {
                    int2 ee = __ldg(&d_csr[p]);
                    uint2 v = __ldcg((const uint2*)&hh_prev[ee.x * BH + lane4]);
                    acc_msg(a01, a23, __int_as_float(ee.y), v);
                }
                float4 r;
                unpack2(a01, r.x, r.y); unpack2(a23, r.z, r.w);
                *(float4*)&agg_s[lnA * BH + lane4] = r;
            }
            if (actB) {
                int p = pB;
                for (; p + 4 <= eB; p += 4) {
                    int2 e0 = __ldg(&d_csr[p]);
                    int2 e1 = __ldg(&d_csr[p + 1]);
                    int2 e2 = __ldg(&d_csr[p + 2]);
                    int2 e3 = __ldg(&d_csr[p + 3]);
                    uint2 v0 = __ldcg((const uint2*)&hh_prev[e0.x * BH + lane4]);
                    uint2 v1 = __ldcg((const uint2*)&hh_prev[e1.x * BH + lane4]);
                    uint2 v2 = __ldcg((const uint2*)&hh_prev[e2.x * BH + lane4]);
                    uint2 v3 = __ldcg((const uint2*)&hh_prev[e3.x * BH + lane4]);
                    acc_msg(b01, b23, __int_as_float(e0.y), v0);
                    acc_msg(b01, b23, __int_as_float(e1.y), v1);
                    acc_msg(b01, b23, __int_as_float(e2.y), v2);
                    acc_msg(b01, b23, __int_as_float(e3.y), v3);
                }
                for (; p < eB; p++) {
                    int2 ee = __ldg(&d_csr[p]);
                    uint2 v = __ldcg((const uint2*)&hh_prev[ee.x * BH + lane4]);
                    acc_msg(b01, b23, __int_as_float(ee.y), v);
                }
                float4 r;
                unpack2(b01, r.x, r.y); unpack2(b23, r.z, r.w);
                *(float4*)&agg_s[lnB * BH + lane4] = r;
            }
        }
        __syncthreads();

        // ---- phase 2: g = agg @ W + b; 4 items/group; conflict-free kp-major W ----
        #pragma unroll
        for (int round = 0; round < 3; round++) {
            int it0 = round * 16 + pg * 4;
            int i0 = it0,     v0 = (i0 < nb2); if (!v0) i0 = 0;
            int i1 = it0 + 1, v1 = (i1 < nb2); if (!v1) i1 = 0;
            int i2 = it0 + 2, v2 = (i2 < nb2); if (!v2) i2 = 0;
            int i3 = it0 + 3, v3 = (i3 < nb2); if (!v3) i3 = 0;
            if (it0 >= nb2) continue;

            u64 G0 = 0, G1 = 0, G2 = 0, G3 = 0;
            #pragma unroll
            for (int k2 = 0; k2 < 16; k2++) {
                u64 w0 = Wp_s[(2 * k2) * 64 + j];        // conflict-free LDS64
                u64 w1 = Wp_s[(2 * k2 + 1) * 64 + j];
                ulonglong2 a0 = *(const ulonglong2*)&agg_s[i0 * 64 + k2 * 4];  // broadcast
                ulonglong2 a1 = *(const ulonglong2*)&agg_s[i1 * 64 + k2 * 4];
                ulonglong2 a2 = *(const ulonglong2*)&agg_s[i2 * 64 + k2 * 4];
                ulonglong2 a3 = *(const ulonglong2*)&agg_s[i3 * 64 + k2 * 4];
                ffma2(G0, a0.x, w0); ffma2(G0, a0.y, w1);
                ffma2(G1, a1.x, w0); ffma2(G1, a1.y, w1);
                ffma2(G2, a2.x, w0); ffma2(G2, a2.y, w1);
                ffma2(G3, a3.x, w0); ffma2(G3, a3.y, w1);
            }

            #define EPILOG(G, ii, vv)                                                 \
                if (vv) {                                                             \
                    float glo, ghi; unpack2(G, glo, ghi);                             \
                    float g = glo + ghi + bias_j;                                     \
                    int bsel = ii & 1;                                                \
                    int nn = node0 + (ii >> 1);                                       \
                    float xr = bsel ? xr1 : xr0;                                      \
                    float xz = bsel ? xz1 : xz0;                                      \
                    float xh = bsel ? xh1 : xh0;                                      \
                    float r = fsigm(xr + g);                                          \
                    float z = fsigm(xz + g);                                          \
                    float ht = ftanh(xh + r * g);                                     \
                    float hold = hs[ii * 64 + j];                                     \
                    float hn = hold + z * (ht - hold);                                \
                    hs[ii * 64 + j] = hn;                                             \
                    __stcg(&hh_next[nn * BH + (bsel << 6) + j], __float2half_rn(hn)); \
                    out[((size_t)(bsel * TT + t) * NN + nn) * Hn + j] = hn;           \
                }
            EPILOG(G0, i0, v0)
            EPILOG(G1, i1, v1)
            EPILOG(G2, i2, v2)
            EPILOG(G3, i3, v3)
            #undef EPILOG
        }

        if (t < TT - 1) grid_barrier();   // hh_next published before next step's gather
    }
}

// ---------------- launch: ONE kernel ----------------
extern "C" void kernel_launch(void* const* d_in, const int* in_sizes, int n_in,
                              void* d_out, int out_size) {
    const float* x    = (const float*)d_in[0];
    const int*   src  = (const int*)  d_in[1];
    const int*   dst  = (const int*)  d_in[2];
    const float* wr   = (const float*)d_in[3];
    const float* br   = (const float*)d_in[4];
    const float* wz   = (const float*)d_in[5];
    const float* bz   = (const float*)d_in[6];
    const float* wh   = (const float*)d_in[7];
    const float* bh   = (const float*)d_in[8];
    const float* gw   = (const float*)d_in[9];
    const float* gb   = (const float*)d_in[10];
    float* out = (float*)d_out;
    int E = in_sizes[1];

    mega_kernel<<<GRID, 256>>>(x, src, dst, wr, br, wz, bz, wh, bh, gw, gb, out, E);
}